// round 17
// baseline (speedup 1.0000x reference)
#include <cuda_runtime.h>
#include <cuda_fp16.h>
#include <math.h>
#include <stdint.h>

#define S_LEN 2048
#define H_DIM 4096
#define NH 32
#define HD 128
#define INNER 16384
#define QKV3 12288   // 3*H

static constexpr float ALPHA   = 7.4833147735478827f;  // sqrt(56)
static constexpr float SCALING = 1.0f;                 // layer_id+1 = 1
static constexpr float COEFF   = 11.313708498984761f;  // sqrt(128)*1
static constexpr float EPS     = 1e-5f;

// ---------------- scratch (device globals; no allocations allowed) ----------
__device__ __align__(1024) float  g_res1  [(size_t)S_LEN * H_DIM];
__device__ __align__(1024) float  g_hidden[(size_t)S_LEN * H_DIM];
__device__ __align__(1024) float  g_res2  [(size_t)S_LEN * H_DIM];

__device__ __align__(1024) __half g_qkvh  [(size_t)S_LEN * QKV3];
__device__ __align__(1024) __half g_res1h [(size_t)S_LEN * H_DIM];
__device__ __align__(1024) __half g_res2h [(size_t)S_LEN * H_DIM];
__device__ __align__(1024) __half g_ctxh  [(size_t)S_LEN * H_DIM];
__device__ __align__(1024) __half g_acth  [(size_t)S_LEN * INNER];

__device__ __align__(1024) __half g_qkv_wh  [(size_t)QKV3 * H_DIM];
__device__ __align__(1024) __half g_dense_wh[(size_t)H_DIM * H_DIM];
__device__ __align__(1024) __half g_w1h     [(size_t)INNER * H_DIM];
__device__ __align__(1024) __half g_w2h     [(size_t)H_DIM * INNER];

// ---------------- helpers ----------------
__device__ __forceinline__ float warpSum(float v) {
    #pragma unroll
    for (int o = 16; o > 0; o >>= 1) v += __shfl_xor_sync(0xffffffffu, v, o);
    return v;
}
__device__ __forceinline__ float gelu_tanh(float x) {
    float x3 = x * x * x;
    return 0.5f * x * (1.f + tanhf(0.7978845608028654f * (x + 0.044715f * x3)));
}

__device__ __forceinline__ void cp_async16(uint32_t sa, const void* g) {
    asm volatile("cp.async.cg.shared.global [%0], [%1], 16;\n" :: "r"(sa), "l"(g));
}
__device__ __forceinline__ void cp_commit() {
    asm volatile("cp.async.commit_group;\n");
}
template <int N>
__device__ __forceinline__ void cp_wait() {
    asm volatile("cp.async.wait_group %0;\n" :: "n"(N));
}

__device__ __forceinline__ void mma_f16(float& c0, float& c1, float& c2, float& c3,
                                        uint32_t a0, uint32_t a1, uint32_t a2, uint32_t a3,
                                        uint32_t b0, uint32_t b1) {
    asm volatile(
        "mma.sync.aligned.m16n8k16.row.col.f32.f16.f16.f32 "
        "{%0,%1,%2,%3}, {%4,%5,%6,%7}, {%8,%9}, {%0,%1,%2,%3};\n"
        : "+f"(c0), "+f"(c1), "+f"(c2), "+f"(c3)
        : "r"(a0), "r"(a1), "r"(a2), "r"(a3), "r"(b0), "r"(b1));
}

__device__ __forceinline__ void ldm_x4(uint32_t& r0, uint32_t& r1,
                                       uint32_t& r2, uint32_t& r3, uint32_t addr) {
    asm volatile("ldmatrix.sync.aligned.m8n8.x4.shared.b16 {%0,%1,%2,%3}, [%4];"
                 : "=r"(r0), "=r"(r1), "=r"(r2), "=r"(r3) : "r"(addr));
}
__device__ __forceinline__ void ldm_x4_trans(uint32_t& r0, uint32_t& r1,
                                             uint32_t& r2, uint32_t& r3, uint32_t addr) {
    asm volatile("ldmatrix.sync.aligned.m8n8.x4.trans.shared.b16 {%0,%1,%2,%3}, [%4];"
                 : "=r"(r0), "=r"(r1), "=r"(r2), "=r"(r3) : "r"(addr));
}

// ---------------- fp32 -> fp16 conversion ----------------
__global__ void f2h_kernel(const float* __restrict__ x, __half* __restrict__ y, int n) {
    int i = (blockIdx.x * blockDim.x + threadIdx.x) * 4;
    if (i < n) {
        float4 v = *(const float4*)(x + i);
        __half2* yo = (__half2*)(y + i);
        yo[0] = __floats2half2_rn(v.x, v.y);
        yo[1] = __floats2half2_rn(v.z, v.w);
    }
}

// ---------------- LayerNorm (fp32 out + fp16 out) ----------------
__global__ void ln_kernel(const float* __restrict__ x,
                          const float* __restrict__ w,
                          const float* __restrict__ b,
                          float* __restrict__ out,
                          __half* __restrict__ outh) {
    int row = blockIdx.x;
    int t = threadIdx.x;
    const float* xr = x + (size_t)row * H_DIM;
    float v[16];
    float s = 0.f;
    #pragma unroll
    for (int i = 0; i < 16; i++) { v[i] = xr[t + i * 256]; s += v[i]; }

    __shared__ float sh[8];
    __shared__ float s_mean, s_rstd;
    int lane = t & 31, wid = t >> 5;

    s = warpSum(s);
    if (lane == 0) sh[wid] = s;
    __syncthreads();
    if (t == 0) {
        float tot = 0.f;
        #pragma unroll
        for (int i = 0; i < 8; i++) tot += sh[i];
        s_mean = tot / (float)H_DIM;
    }
    __syncthreads();
    float m = s_mean;

    float vs = 0.f;
    #pragma unroll
    for (int i = 0; i < 16; i++) { float d = v[i] - m; vs += d * d; }
    vs = warpSum(vs);
    __syncthreads();
    if (lane == 0) sh[wid] = vs;
    __syncthreads();
    if (t == 0) {
        float tot = 0.f;
        #pragma unroll
        for (int i = 0; i < 8; i++) tot += sh[i];
        s_rstd = rsqrtf(tot / (float)H_DIM + EPS);
    }
    __syncthreads();
    float r = s_rstd;

    float* orow = out + (size_t)row * H_DIM;
    __half* hrow = outh + (size_t)row * H_DIM;
    #pragma unroll
    for (int i = 0; i < 16; i++) {
        int c = t + i * 256;
        float o = (v[i] - m) * r * w[c] + b[c];
        orow[c] = o;
        hrow[c] = __float2half_rn(o);
    }
}

// ---------------- RoPE (GLM dual rotary), fp16 in-place on qkvh -------------
__global__ void rope_h_kernel(__half* __restrict__ qkv,
                              const float* __restrict__ cosc,
                              const float* __restrict__ sinc) {
    int s = blockIdx.x, h = blockIdx.y;
    __half* base = qkv + (size_t)s * QKV3 + h * 384;
    __shared__ float buf[256];
    int t = threadIdx.x;
    buf[t] = __half2float(base[t]);
    __syncthreads();

    int isK  = (t >= 128) ? 128 : 0;
    int d    = t & 127;
    int half = d >> 6;
    int dd   = d & 63;

    int pos;
    if (half == 0) pos = (s < S_LEN - 1) ? s : (S_LEN - 2);
    else           pos = (s == S_LEN - 1) ? 1 : 0;

    float c  = cosc[pos * 64 + dd];
    float sn = sinc[pos * 64 + dd];

    int boff = isK + half * 64;
    float x   = buf[boff + dd];
    float rot = (dd < 32) ? -buf[boff + dd + 32] : buf[boff + dd - 32];
    base[t] = __float2half_rn(x * c + rot * sn);
}

// ============== HMMA flash attention: 128q CTA, 64-key tiles ================
#define KVSTR 272
#define TILE_B (64 * KVSTR)          // 17408
#define ATTN_SMEM (2 * 2 * TILE_B)   // 69632

__global__ void __launch_bounds__(256, 1)
fattn_mma(const __half* __restrict__ qkv, __half* __restrict__ ctx) {
    extern __shared__ char smem[];
    const uint32_t sbase = (uint32_t)__cvta_generic_to_shared(smem);
    const int tid  = threadIdx.x;
    const int lane = tid & 31;
    const int wid  = tid >> 5;
    const int g    = lane >> 2;
    const int c    = lane & 3;
    const int qb   = blockIdx.x * 128 + wid * 16;
    const int h    = blockIdx.y;

    // Q fragments (held in registers for all K tiles)
    uint32_t qf[8][4];
    {
        const __half* q0 = qkv + (size_t)(qb + g) * QKV3 + h * 384;
        const __half* q8 = q0 + (size_t)8 * QKV3;
        #pragma unroll
        for (int kc = 0; kc < 8; kc++) {
            qf[kc][0] = *(const uint32_t*)(q0 + kc * 16 + 2 * c);
            qf[kc][1] = *(const uint32_t*)(q8 + kc * 16 + 2 * c);
            qf[kc][2] = *(const uint32_t*)(q0 + kc * 16 + 2 * c + 8);
            qf[kc][3] = *(const uint32_t*)(q8 + kc * 16 + 2 * c + 8);
        }
    }

    float oacc[16][4];
    #pragma unroll
    for (int dn = 0; dn < 16; dn++)
        #pragma unroll
        for (int q = 0; q < 4; q++) oacc[dn][q] = 0.f;
    float m0 = -1e30f, m1 = -1e30f, l0 = 0.f, l1 = 0.f;

    auto load_tile = [&](int kt, int b) {
        uint32_t kb = sbase + (uint32_t)b * (2 * TILE_B);
        uint32_t vb = kb + TILE_B;
        const int kbase = kt * 64;
        #pragma unroll
        for (int i = 0; i < 4; i++) {
            int id = tid + 256 * i;
            int row = id >> 4, ch = id & 15;
            const __half* src = qkv + (size_t)(kbase + row) * QKV3 + h * 384 + 128 + ch * 8;
            cp_async16(kb + (uint32_t)row * KVSTR + ch * 16, src);
            cp_async16(vb + (uint32_t)row * KVSTR + ch * 16, src + 128);
        }
        cp_commit();
    };

    load_tile(0, 0);
    const float C1 = 0.12752697f;   // log2(e) * SCALING / COEFF

    for (int kt = 0; kt < S_LEN / 64; kt++) {
        const int b = kt & 1;
        if (kt + 1 < S_LEN / 64) { load_tile(kt + 1, b ^ 1); cp_wait<1>(); }
        else                     cp_wait<0>();
        __syncthreads();

        const uint32_t kbb = sbase + (uint32_t)b * (2 * TILE_B);
        const uint32_t vbase = kbb + TILE_B;

        // S = Q K^T  (8 n-tiles of 8 keys); b-frags via ldmatrix.x4
        float sacc[8][4];
        #pragma unroll
        for (int j = 0; j < 8; j++) {
            sacc[j][0] = sacc[j][1] = sacc[j][2] = sacc[j][3] = 0.f;
            #pragma unroll
            for (int kc = 0; kc < 8; kc += 2) {
                uint32_t addr = kbb + (uint32_t)(j * 8 + (lane & 7)) * KVSTR
                              + kc * 32 + (lane >> 3) * 16;
                uint32_t b0, b1, b2, b3;
                ldm_x4(b0, b1, b2, b3, addr);
                mma_f16(sacc[j][0], sacc[j][1], sacc[j][2], sacc[j][3],
                        qf[kc][0], qf[kc][1], qf[kc][2], qf[kc][3], b0, b1);
                mma_f16(sacc[j][0], sacc[j][1], sacc[j][2], sacc[j][3],
                        qf[kc + 1][0], qf[kc + 1][1], qf[kc + 1][2], qf[kc + 1][3], b2, b3);
            }
        }

        // online softmax (rows g and g+8)
        float ml0 = -1e30f, ml1 = -1e30f;
        #pragma unroll
        for (int j = 0; j < 8; j++) {
            ml0 = fmaxf(ml0, fmaxf(sacc[j][0], sacc[j][1]));
            ml1 = fmaxf(ml1, fmaxf(sacc[j][2], sacc[j][3]));
        }
        ml0 = fmaxf(ml0, __shfl_xor_sync(0xffffffffu, ml0, 1));
        ml0 = fmaxf(ml0, __shfl_xor_sync(0xffffffffu, ml0, 2));
        ml1 = fmaxf(ml1, __shfl_xor_sync(0xffffffffu, ml1, 1));
        ml1 = fmaxf(ml1, __shfl_xor_sync(0xffffffffu, ml1, 2));

        float mn0 = fmaxf(m0, ml0), mn1 = fmaxf(m1, ml1);
        float f0 = exp2f((m0 - mn0) * C1), f1 = exp2f((m1 - mn1) * C1);
        m0 = mn0; m1 = mn1;
        const float mc0 = mn0 * C1, mc1 = mn1 * C1;

        uint32_t p01[8], p23[8];
        float ls0 = 0.f, ls1 = 0.f;
        #pragma unroll
        for (int j = 0; j < 8; j++) {
            __half2 e0 = __floats2half2_rn(fmaf(sacc[j][0], C1, -mc0),
                                           fmaf(sacc[j][1], C1, -mc0));
            __half2 e1 = __floats2half2_rn(fmaf(sacc[j][2], C1, -mc1),
                                           fmaf(sacc[j][3], C1, -mc1));
            uint32_t u0 = *(uint32_t*)&e0, u1 = *(uint32_t*)&e1;
            uint32_t r0, r1;
            asm("ex2.approx.f16x2 %0, %1;" : "=r"(r0) : "r"(u0));
            asm("ex2.approx.f16x2 %0, %1;" : "=r"(r1) : "r"(u1));
            p01[j] = r0; p23[j] = r1;
            float2 fA = __half22float2(*(__half2*)&r0);
            float2 fB = __half22float2(*(__half2*)&r1);
            ls0 += fA.x + fA.y;
            ls1 += fB.x + fB.y;
        }
        l0 = l0 * f0 + ls0;
        l1 = l1 * f1 + ls1;
        #pragma unroll
        for (int dn = 0; dn < 16; dn++) {
            oacc[dn][0] *= f0; oacc[dn][1] *= f0;
            oacc[dn][2] *= f1; oacc[dn][3] *= f1;
        }

        // O += P V : b-frags via ldmatrix.x4.trans (covers dn, dn+1)
        #pragma unroll
        for (int kk = 0; kk < 4; kk++) {
            uint32_t a0 = p01[2 * kk], a1 = p23[2 * kk];
            uint32_t a2 = p01[2 * kk + 1], a3 = p23[2 * kk + 1];
            #pragma unroll
            for (int dn = 0; dn < 16; dn += 2) {
                uint32_t addr = vbase + (uint32_t)(kk * 16 + (lane & 15)) * KVSTR
                              + (dn + (lane >> 4)) * 16;
                uint32_t b0, b1, b2, b3;
                ldm_x4_trans(b0, b1, b2, b3, addr);
                mma_f16(oacc[dn][0], oacc[dn][1], oacc[dn][2], oacc[dn][3],
                        a0, a1, a2, a3, b0, b1);
                mma_f16(oacc[dn + 1][0], oacc[dn + 1][1], oacc[dn + 1][2], oacc[dn + 1][3],
                        a0, a1, a2, a3, b2, b3);
            }
        }
        __syncthreads();
    }

    l0 += __shfl_xor_sync(0xffffffffu, l0, 1);
    l0 += __shfl_xor_sync(0xffffffffu, l0, 2);
    l1 += __shfl_xor_sync(0xffffffffu, l1, 1);
    l1 += __shfl_xor_sync(0xffffffffu, l1, 2);
    const float inv0 = 1.f / l0, inv1 = 1.f / l1;

    __half* c0row = ctx + (size_t)(qb + g) * H_DIM + h * HD;
    __half* c8row = c0row + (size_t)8 * H_DIM;
    #pragma unroll
    for (int dn = 0; dn < 16; dn++) {
        *(__half2*)(c0row + dn * 8 + 2 * c) =
            __floats2half2_rn(oacc[dn][0] * inv0, oacc[dn][1] * inv0);
        *(__half2*)(c8row + dn * 8 + 2 * c) =
            __floats2half2_rn(oacc[dn][2] * inv1, oacc[dn][3] * inv1);
    }
}

// ====== fp16 HMMA GEMM, 512 threads (16 warps), 128x256 tile: C = A*B^T =====
#define BK 32
#define AST 80
#define A_SBYTES (128 * AST)
#define B_SBYTES (256 * AST)
#define BUF_SBYTES (A_SBYTES + B_SBYTES)
#define NBUF 3
#define GEMM_SMEM_BYTES (NBUF * BUF_SBYTES)

template <int EPI, int OUTH>
__global__ void __launch_bounds__(512, 1)
gemm_h(const __half* __restrict__ A, const __half* __restrict__ B,
       const float* __restrict__ bias, const float* __restrict__ res,
       float alpha, void* __restrict__ Cv, int M, int N, int K) {
    extern __shared__ char smem[];

    const int tid  = threadIdx.x;
    const int lane = tid & 31;
    const int wid  = tid >> 5;          // 0..15
    const int wm   = wid & 1;           // 0..1  -> 64-row slab
    const int wn   = wid >> 1;          // 0..7  -> 32-col slab
    const int g    = lane >> 2;
    const int c    = lane & 3;

    const int m0 = blockIdx.x * 128;
    const int n0 = blockIdx.y * 256;

    const uint32_t sbase = (uint32_t)__cvta_generic_to_shared(smem);
    const int row4 = tid >> 2;          // 0..127
    const int kc   = tid & 3;

    float acc[4][4][4];
    #pragma unroll
    for (int i = 0; i < 4; i++)
        #pragma unroll
        for (int j = 0; j < 4; j++)
            #pragma unroll
            for (int q = 0; q < 4; q++) acc[i][j][q] = 0.f;

    const int nk = K >> 5;

    auto issue = [&](int kt, int b) {
        uint32_t ab = sbase + (uint32_t)b * BUF_SBYTES;
        uint32_t bb = ab + A_SBYTES;
        const __half* ag = A + (size_t)(m0 + row4) * K + kt * BK + kc * 8;
        const __half* bg = B + (size_t)(n0 + row4) * K + kt * BK + kc * 8;
        cp_async16(ab + (uint32_t)row4 * AST + kc * 16, ag);
        #pragma unroll
        for (int i = 0; i < 2; i++)
            cp_async16(bb + (uint32_t)(row4 + 128 * i) * AST + kc * 16,
                       bg + (size_t)(128 * i) * K);
        cp_commit();
    };

    issue(0, 0);
    issue(1, 1);

    // ldmatrix address components (constant per thread)
    const int a_row = wm * 64 + (lane & 15);      // + mt*16
    const int a_cb  = (lane & 16);                // 0 | 16 bytes
    const int b_row = wn * 32 + (lane & 7) + ((lane >> 4) << 3);  // + nt*8 (pairs)
    const int b_cb  = ((lane >> 3) & 1) * 16;     // 0 | 16 bytes

    for (int kt = 0; kt < nk; kt++) {
        const int b = kt % NBUF;
        if (kt + 2 < nk) { issue(kt + 2, (kt + 2) % NBUF); cp_wait<2>(); }
        else if (kt + 1 < nk) cp_wait<1>();
        else cp_wait<0>();
        __syncthreads();

        const uint32_t As = sbase + (uint32_t)b * BUF_SBYTES;
        const uint32_t Bs = As + A_SBYTES;

        #pragma unroll
        for (int ks = 0; ks < 2; ks++) {
            const int kb = ks * 32;
            uint32_t af[4][4];
            uint32_t bf[4][2];
            #pragma unroll
            for (int mt = 0; mt < 4; mt++)
                ldm_x4(af[mt][0], af[mt][1], af[mt][2], af[mt][3],
                       As + (uint32_t)(a_row + mt * 16) * AST + kb + a_cb);
            #pragma unroll
            for (int nt = 0; nt < 4; nt += 2)
                ldm_x4(bf[nt][0], bf[nt][1], bf[nt + 1][0], bf[nt + 1][1],
                       Bs + (uint32_t)(b_row + nt * 8) * AST + kb + b_cb);
            #pragma unroll
            for (int mt = 0; mt < 4; mt++)
                #pragma unroll
                for (int nt = 0; nt < 4; nt++)
                    mma_f16(acc[mt][nt][0], acc[mt][nt][1],
                            acc[mt][nt][2], acc[mt][nt][3],
                            af[mt][0], af[mt][1], af[mt][2], af[mt][3],
                            bf[nt][0], bf[nt][1]);
        }
        __syncthreads();
    }

    #pragma unroll
    for (int mt = 0; mt < 4; mt++) {
        int r0 = m0 + wm * 64 + mt * 16 + g;
        int r1 = r0 + 8;
        #pragma unroll
        for (int nt = 0; nt < 4; nt++) {
            int col = n0 + wn * 32 + nt * 8 + 2 * c;
            float b0v = bias[col], b1v = bias[col + 1];

            float v0 = acc[mt][nt][0] + b0v;
            float v1 = acc[mt][nt][1] + b1v;
            float v2 = acc[mt][nt][2] + b0v;
            float v3 = acc[mt][nt][3] + b1v;
            if (EPI == 1) {
                v0 = gelu_tanh(v0); v1 = gelu_tanh(v1);
                v2 = gelu_tanh(v2); v3 = gelu_tanh(v3);
            }
            if (EPI == 2) {
                const float* rr0 = res + (size_t)r0 * N + col;
                const float* rr1 = res + (size_t)r1 * N + col;
                v0 += alpha * rr0[0]; v1 += alpha * rr0[1];
                v2 += alpha * rr1[0]; v3 += alpha * rr1[1];
            }
            if (OUTH) {
                __half* C = (__half*)Cv;
                *(__half2*)(C + (size_t)r0 * N + col) = __floats2half2_rn(v0, v1);
                *(__half2*)(C + (size_t)r1 * N + col) = __floats2half2_rn(v2, v3);
            } else {
                float* C = (float*)Cv;
                *(float2*)(C + (size_t)r0 * N + col) = make_float2(v0, v1);
                *(float2*)(C + (size_t)r1 * N + col) = make_float2(v2, v3);
            }
        }
    }
}

// ---------------- launch ----------------------------------------------------
extern "C" void kernel_launch(void* const* d_in, const int* in_sizes, int n_in,
                              void* d_out, int out_size) {
    const float* hidden  = (const float*)d_in[0];
    const float* cosc    = (const float*)d_in[4];
    const float* sinc    = (const float*)d_in[5];
    const float* ln1_w   = (const float*)d_in[6];
    const float* ln1_b   = (const float*)d_in[7];
    const float* qkv_w   = (const float*)d_in[8];
    const float* qkv_b   = (const float*)d_in[9];
    const float* dense_w = (const float*)d_in[10];
    const float* dense_b = (const float*)d_in[11];
    const float* ln2_w   = (const float*)d_in[12];
    const float* ln2_b   = (const float*)d_in[13];
    const float* mlp_w1  = (const float*)d_in[14];
    const float* mlp_b1  = (const float*)d_in[15];
    const float* mlp_w2  = (const float*)d_in[16];
    const float* mlp_b2  = (const float*)d_in[17];
    float* out = (float*)d_out;

    float *res1, *hid, *res2;
    __half *qkvh, *res1h, *res2h, *ctxh, *acth, *qkv_wh, *dense_wh, *w1h, *w2h;
    cudaGetSymbolAddress((void**)&res1,  g_res1);
    cudaGetSymbolAddress((void**)&hid,   g_hidden);
    cudaGetSymbolAddress((void**)&res2,  g_res2);
    cudaGetSymbolAddress((void**)&qkvh,  g_qkvh);
    cudaGetSymbolAddress((void**)&res1h, g_res1h);
    cudaGetSymbolAddress((void**)&res2h, g_res2h);
    cudaGetSymbolAddress((void**)&ctxh,  g_ctxh);
    cudaGetSymbolAddress((void**)&acth,  g_acth);
    cudaGetSymbolAddress((void**)&qkv_wh,   g_qkv_wh);
    cudaGetSymbolAddress((void**)&dense_wh, g_dense_wh);
    cudaGetSymbolAddress((void**)&w1h,      g_w1h);
    cudaGetSymbolAddress((void**)&w2h,      g_w2h);

    cudaFuncSetAttribute(gemm_h<0,1>, cudaFuncAttributeMaxDynamicSharedMemorySize, GEMM_SMEM_BYTES);
    cudaFuncSetAttribute(gemm_h<1,1>, cudaFuncAttributeMaxDynamicSharedMemorySize, GEMM_SMEM_BYTES);
    cudaFuncSetAttribute(gemm_h<2,0>, cudaFuncAttributeMaxDynamicSharedMemorySize, GEMM_SMEM_BYTES);
    cudaFuncSetAttribute(fattn_mma,   cudaFuncAttributeMaxDynamicSharedMemorySize, ATTN_SMEM);

    // --- side stream for weight conversions not needed until the dense GEMM ---
    cudaStream_t s1;
    cudaStreamCreateWithFlags(&s1, cudaStreamNonBlocking);
    cudaEvent_t eFork, eJoin;
    cudaEventCreateWithFlags(&eFork, cudaEventDisableTiming);
    cudaEventCreateWithFlags(&eJoin, cudaEventDisableTiming);

    cudaEventRecord(eFork, 0);
    cudaStreamWaitEvent(s1, eFork, 0);
    {
        int n;
        n = H_DIM * H_DIM; f2h_kernel<<<n / 1024, 256, 0, s1>>>(dense_w, dense_wh, n);
        n = INNER * H_DIM; f2h_kernel<<<n / 1024, 256, 0, s1>>>(mlp_w1,  w1h,      n);
        n = H_DIM * INNER; f2h_kernel<<<n / 1024, 256, 0, s1>>>(mlp_w2,  w2h,      n);
    }
    cudaEventRecord(eJoin, s1);

    // --- main chain ---
    // 0. qkv weight conversion (needed first)
    {
        int n = QKV3 * H_DIM;
        f2h_kernel<<<n / 1024, 256>>>(qkv_w, qkv_wh, n);
    }

    // 1. LN1
    ln_kernel<<<S_LEN, 256>>>(hidden, ln1_w, ln1_b, res1, res1h);

    // 2. QKV GEMM -> fp16 qkvh
    {
        dim3 grid(S_LEN / 128, QKV3 / 256);
        gemm_h<0,1><<<grid, 512, GEMM_SMEM_BYTES>>>(res1h, qkv_wh, qkv_b, res1, 0.f,
                                                    qkvh, S_LEN, QKV3, H_DIM);
    }

    // 3. RoPE (fp16 in-place)
    {
        dim3 grid(S_LEN, NH);
        rope_h_kernel<<<grid, 256>>>(qkvh, cosc, sinc);
    }

    // 4. HMMA flash attention (fp16 ctx out)
    {
        dim3 grid(S_LEN / 128, NH);
        fattn_mma<<<grid, 256, ATTN_SMEM>>>(qkvh, ctxh);
    }

    // join: dense/MLP weight conversions must be done from here on
    cudaStreamWaitEvent(0, eJoin, 0);

    // 5. dense GEMM + alpha*residual
    {
        dim3 grid(S_LEN / 128, H_DIM / 256);
        gemm_h<2,0><<<grid, 512, GEMM_SMEM_BYTES>>>(ctxh, dense_wh, dense_b, res1, ALPHA,
                                                    hid, S_LEN, H_DIM, H_DIM);
    }

    // 6. LN2
    ln_kernel<<<S_LEN, 256>>>(hid, ln2_w, ln2_b, res2, res2h);

    // 7. MLP up + gelu (fp16 out)
    {
        dim3 grid(S_LEN / 128, INNER / 256);
        gemm_h<1,1><<<grid, 512, GEMM_SMEM_BYTES>>>(res2h, w1h, mlp_b1, res2, 0.f,
                                                    acth, S_LEN, INNER, H_DIM);
    }

    // 8. MLP down + alpha*residual -> output
    {
        dim3 grid(S_LEN / 128, H_DIM / 256);
        gemm_h<2,0><<<grid, 512, GEMM_SMEM_BYTES>>>(acth, w2h, mlp_b2, res2, ALPHA,
                                                    out, S_LEN, H_DIM, INNER);
    }

    cudaEventDestroy(eFork);
    cudaEventDestroy(eJoin);
    cudaStreamDestroy(s1);
}